// round 2
// baseline (speedup 1.0000x reference)
#include <cuda_runtime.h>

#define TMAXB 100000
#define SCAN_THREADS 1024

// Per-time-bucket accumulators (all L2-resident: ~2.4 MB total)
__device__ float g_hz[TMAXB];      // sum exp(lh) per time
__device__ int   g_m[TMAXB];       // event count per time
__device__ float g_lognom[TMAXB];  // sum lh*ev per time
__device__ float g_ties[TMAXB];    // sum exp(lh)*ev per time
__device__ float g_denom[TMAXB];   // suffix sum of g_hz (risk set)
__device__ int   g_rank[TMAXB];    // rank counters for Efron term
__device__ double g_sum_terms;     // sum over events of log(D - (l/m)T)
__device__ double g_sum_lognom;    // sum of lognom over buckets with m>0
__device__ int    g_include;       // count of buckets with m>0

// ---------------------------------------------------------------------------
__global__ void k_zero() {
    int i = blockIdx.x * blockDim.x + threadIdx.x;
    if (i < TMAXB) {
        g_hz[i] = 0.f; g_m[i] = 0; g_lognom[i] = 0.f;
        g_ties[i] = 0.f; g_rank[i] = 0;
    }
    if (i == 0) { g_sum_terms = 0.0; g_sum_lognom = 0.0; g_include = 0; }
}

// ---------------------------------------------------------------------------
// Pass 1: per-sample bucket accumulation (atomics to L2-resident arrays)
__global__ void k_accum(const float* __restrict__ lh,
                        const int*   __restrict__ tt,
                        const int*   __restrict__ ev, int n) {
    int i = blockIdx.x * blockDim.x + threadIdx.x;
    int stride = gridDim.x * blockDim.x;
    for (; i < n; i += stride) {
        float x = lh[i];
        int   t = tt[i];
        float h = expf(x);
        atomicAdd(&g_hz[t], h);
        if (ev[i]) {
            atomicAdd(&g_m[t], 1);
            atomicAdd(&g_lognom[t], x);
            atomicAdd(&g_ties[t], h);
        }
    }
}

// ---------------------------------------------------------------------------
// Suffix sum of g_hz -> g_denom. Single block; each thread owns a contiguous
// chunk, one block-wide suffix scan of chunk totals, then per-thread walk.
__global__ void k_scan() {
    const int B = SCAN_THREADS;
    int tid = threadIdx.x;
    const int chunk = (TMAXB + B - 1) / B;  // 98
    int lo = tid * chunk;
    int hi = lo + chunk; if (hi > TMAXB) hi = TMAXB;
    if (lo > TMAXB) lo = TMAXB;

    float s = 0.f;
    for (int j = lo; j < hi; ++j) s += g_hz[j];

    __shared__ float sa[SCAN_THREADS];
    __shared__ float sb[SCAN_THREADS];
    sa[tid] = s;
    __syncthreads();
    // inclusive SUFFIX scan over threads (Hillis-Steele, double-buffered)
    float* src = sa; float* dst = sb;
    for (int off = 1; off < B; off <<= 1) {
        float v = src[tid];
        if (tid + off < B) v += src[tid + off];
        dst[tid] = v;
        __syncthreads();
        float* tmp = src; src = dst; dst = tmp;
    }
    float suf_incl = src[tid];        // sum over threads >= tid
    float run = suf_incl - s;         // exclusive: threads > tid
    for (int j = hi - 1; j >= lo; --j) {
        run += g_hz[j];
        g_denom[j] = run;
    }
}

// ---------------------------------------------------------------------------
__device__ __forceinline__ double block_reduce_d(double v) {
    __shared__ double sh[32];
    int lane = threadIdx.x & 31, wid = threadIdx.x >> 5;
    #pragma unroll
    for (int o = 16; o > 0; o >>= 1)
        v += __shfl_down_sync(0xffffffffu, v, o);
    if (lane == 0) sh[wid] = v;
    __syncthreads();
    int nw = (blockDim.x + 31) >> 5;
    v = (threadIdx.x < nw) ? sh[threadIdx.x] : 0.0;
    if (wid == 0) {
        #pragma unroll
        for (int o = 16; o > 0; o >>= 1)
            v += __shfl_down_sync(0xffffffffu, v, o);
    }
    return v;
}

// Pass 2: per-event Efron term. Rank assigned by atomic counter (the sum over
// l = 0..m-1 is order-invariant, so any rank assignment order is correct).
__global__ void k_terms(const float* __restrict__ lh,
                        const int*   __restrict__ tt,
                        const int*   __restrict__ ev, int n) {
    int i = blockIdx.x * blockDim.x + threadIdx.x;
    int stride = gridDim.x * blockDim.x;
    double local = 0.0;
    for (; i < n; i += stride) {
        if (ev[i]) {
            int t = tt[i];
            int r = atomicAdd(&g_rank[t], 1);
            float m = (float)g_m[t];
            float arg = g_denom[t] - ((float)r / m) * g_ties[t];
            local += (double)logf(arg);
        }
    }
    double tot = block_reduce_d(local);
    if (threadIdx.x == 0 && tot != 0.0) atomicAdd(&g_sum_terms, tot);
}

// ---------------------------------------------------------------------------
// Bucket pass: sum lognom over buckets with events; count included buckets.
__global__ void k_bucket() {
    int i = blockIdx.x * blockDim.x + threadIdx.x;
    int stride = gridDim.x * blockDim.x;
    double local = 0.0;
    int cnt = 0;
    for (; i < TMAXB; i += stride) {
        if (g_m[i] > 0) { local += (double)g_lognom[i]; cnt++; }
    }
    double tot = block_reduce_d(local);
    // reduce count via shuffle too (reuse double path for simplicity)
    double dcnt = block_reduce_d((double)cnt);
    if (threadIdx.x == 0) {
        if (tot != 0.0) atomicAdd(&g_sum_lognom, tot);
        int ic = (int)(dcnt + 0.5);
        if (ic) atomicAdd(&g_include, ic);
    }
}

// ---------------------------------------------------------------------------
__global__ void k_final(float* out) {
    double pll = g_sum_lognom - g_sum_terms;
    out[0] = (float)(-(pll / (double)g_include));
}

// ---------------------------------------------------------------------------
extern "C" void kernel_launch(void* const* d_in, const int* in_sizes, int n_in,
                              void* d_out, int out_size) {
    const float* lh = (const float*)d_in[0];
    const int*   tt = (const int*)d_in[1];
    const int*   ev = (const int*)d_in[2];
    float* out = (float*)d_out;
    int n = in_sizes[0];

    k_zero<<<(TMAXB + 255) / 256, 256>>>();

    int blocks = 2048;
    k_accum<<<blocks, 256>>>(lh, tt, ev, n);

    k_scan<<<1, SCAN_THREADS>>>();

    k_terms<<<blocks, 256>>>(lh, tt, ev, n);

    k_bucket<<<128, 256>>>();

    k_final<<<1, 1>>>(out);
}

// round 3
// speedup vs baseline: 1.5816x; 1.5816x over previous
#include <cuda_runtime.h>

#define TMAXB 100000

// AoS per-bucket accumulators: {x=hz sum, y=ties sum, z=lognom sum, w=event count}
__device__ float4 g_b[TMAXB];          // 1.6 MB, L2-resident
__device__ float  g_denom[TMAXB];      // suffix sum of hz (risk set)
__device__ double g_sum_terms;         // sum over events of log(D - (l/m)T)
__device__ double g_sum_lognom;        // sum of lognom over buckets with m>0
__device__ int    g_include;           // count of buckets with m>0

// ---------------------------------------------------------------------------
__global__ void k_zero() {
    int i = blockIdx.x * blockDim.x + threadIdx.x;
    if (i < TMAXB) g_b[i] = make_float4(0.f, 0.f, 0.f, 0.f);
    if (i == 0) { g_sum_terms = 0.0; g_sum_lognom = 0.0; g_include = 0; }
}

// ---------------------------------------------------------------------------
// Pass 1: one 16B vector reduction per sample: {h, ev*h, ev*x, ev}
__device__ __forceinline__ void red_v4(float4* p, float a, float b, float c, float d) {
    asm volatile("red.global.add.v4.f32 [%0], {%1,%2,%3,%4};"
                 :: "l"(p), "f"(a), "f"(b), "f"(c), "f"(d) : "memory");
}

__global__ void k_accum(const float4* __restrict__ lh4,
                        const int4*   __restrict__ tt4,
                        const int4*   __restrict__ ev4, int n4) {
    int i = blockIdx.x * blockDim.x + threadIdx.x;
    int stride = gridDim.x * blockDim.x;
    for (; i < n4; i += stride) {
        float4 x = lh4[i];
        int4   t = tt4[i];
        int4   e = ev4[i];
        float h0 = expf(x.x), h1 = expf(x.y), h2 = expf(x.z), h3 = expf(x.w);
        float e0 = (float)e.x, e1 = (float)e.y, e2 = (float)e.z, e3 = (float)e.w;
        red_v4(&g_b[t.x], h0, e0 * h0, e0 * x.x, e0);
        red_v4(&g_b[t.y], h1, e1 * h1, e1 * x.y, e1);
        red_v4(&g_b[t.z], h2, e2 * h2, e2 * x.z, e2);
        red_v4(&g_b[t.w], h3, e3 * h3, e3 * x.w, e3);
    }
}

// tail for n not divisible by 4
__global__ void k_accum_tail(const float* __restrict__ lh,
                             const int*   __restrict__ tt,
                             const int*   __restrict__ ev, int lo, int n) {
    int i = lo + blockIdx.x * blockDim.x + threadIdx.x;
    if (i < n) {
        float x = lh[i];
        float h = expf(x);
        float e = (float)ev[i];
        red_v4(&g_b[tt[i]], h, e * h, e * x, e);
    }
}

// ---------------------------------------------------------------------------
// Suffix sum of g_b[].x -> g_denom. Single block, chunked.
#define SCAN_THREADS 1024
__global__ void k_scan() {
    const int B = SCAN_THREADS;
    int tid = threadIdx.x;
    const int chunk = (TMAXB + B - 1) / B;  // 98
    int lo = tid * chunk;
    int hi = lo + chunk; if (hi > TMAXB) hi = TMAXB;
    if (lo > TMAXB) lo = TMAXB;

    float s = 0.f;
    for (int j = lo; j < hi; ++j) s += g_b[j].x;

    __shared__ float sa[SCAN_THREADS];
    __shared__ float sb[SCAN_THREADS];
    sa[tid] = s;
    __syncthreads();
    float* src = sa; float* dst = sb;
    for (int off = 1; off < B; off <<= 1) {
        float v = src[tid];
        if (tid + off < B) v += src[tid + off];
        dst[tid] = v;
        __syncthreads();
        float* tmp = src; src = dst; dst = tmp;
    }
    float run = src[tid] - s;   // exclusive suffix (threads > tid)
    for (int j = hi - 1; j >= lo; --j) {
        run += g_b[j].x;
        g_denom[j] = run;
    }
}

// ---------------------------------------------------------------------------
__device__ __forceinline__ double block_reduce_d(double v) {
    __shared__ double sh[32];
    int lane = threadIdx.x & 31, wid = threadIdx.x >> 5;
    #pragma unroll
    for (int o = 16; o > 0; o >>= 1)
        v += __shfl_down_sync(0xffffffffu, v, o);
    if (lane == 0) sh[wid] = v;
    __syncthreads();
    int nw = (blockDim.x + 31) >> 5;
    v = (threadIdx.x < nw) ? sh[threadIdx.x] : 0.0;
    if (wid == 0) {
        #pragma unroll
        for (int o = 16; o > 0; o >>= 1)
            v += __shfl_down_sync(0xffffffffu, v, o);
    }
    return v;
}

// ---------------------------------------------------------------------------
// Per-bucket Efron terms: for bucket t with m>0,
//   terms_t = sum_{l=0}^{m-1} log(D - (l/m)*T)
// computed by folding 4 factors into one product per logf.
// Also accumulates sum(lognom) and the include count.
__global__ void k_bucket() {
    int i = blockIdx.x * blockDim.x + threadIdx.x;
    double local_terms = 0.0;
    double local_lognom = 0.0;
    int cnt = 0;
    if (i < TMAXB) {
        float4 b = g_b[i];
        int m = (int)(b.w + 0.5f);
        if (m > 0) {
            cnt = 1;
            local_lognom = (double)b.z;
            float D = g_denom[i];
            float T = b.y;
            float step = T / (float)m;   // (l/m)*T increments
            float arg = D;               // l = 0 term
            int l = 0;
            while (l < m) {
                float prod = 1.0f;
                int lim = (m - l) < 4 ? (m - l) : 4;
                #pragma unroll 4
                for (int j = 0; j < lim; ++j) {
                    prod *= arg;
                    arg -= step;
                }
                local_terms += (double)logf(prod);
                l += lim;
            }
        }
    }
    double t_terms = block_reduce_d(local_terms);
    double t_logn  = block_reduce_d(local_lognom);
    double t_cnt   = block_reduce_d((double)cnt);
    if (threadIdx.x == 0) {
        if (t_terms != 0.0) atomicAdd(&g_sum_terms, t_terms);
        if (t_logn  != 0.0) atomicAdd(&g_sum_lognom, t_logn);
        int ic = (int)(t_cnt + 0.5);
        if (ic) atomicAdd(&g_include, ic);
    }
}

// ---------------------------------------------------------------------------
__global__ void k_final(float* out) {
    double pll = g_sum_lognom - g_sum_terms;
    out[0] = (float)(-(pll / (double)g_include));
}

// ---------------------------------------------------------------------------
extern "C" void kernel_launch(void* const* d_in, const int* in_sizes, int n_in,
                              void* d_out, int out_size) {
    const float* lh = (const float*)d_in[0];
    const int*   tt = (const int*)d_in[1];
    const int*   ev = (const int*)d_in[2];
    float* out = (float*)d_out;
    int n = in_sizes[0];
    int n4 = n / 4;
    int tail = n - n4 * 4;

    k_zero<<<(TMAXB + 255) / 256, 256>>>();

    k_accum<<<2048, 256>>>((const float4*)lh, (const int4*)tt, (const int4*)ev, n4);
    if (tail > 0)
        k_accum_tail<<<1, 256>>>(lh, tt, ev, n4 * 4, n);

    k_scan<<<1, SCAN_THREADS>>>();

    k_bucket<<<(TMAXB + 255) / 256, 256>>>();

    k_final<<<1, 1>>>(out);
}